// round 1
// baseline (speedup 1.0000x reference)
#include <cuda_runtime.h>
#include <cstdint>

#define N_NODES 50000
#define D 128
#define N_EDGES 625000

// Scratch (no cudaMalloc allowed): neighbor-sum and degree accumulators.
__device__ float g_sum[(size_t)N_NODES * D];   // 25.6 MB
__device__ float g_deg[N_NODES];

// ---------------------------------------------------------------------------
// Kernel 1: zero the accumulators (graph replays require re-zeroing each call)
// ---------------------------------------------------------------------------
__global__ void zero_kernel() {
    int i = blockIdx.x * blockDim.x + threadIdx.x;
    const int n4 = N_NODES * D / 4;  // 1,600,000 float4
    float4 z = make_float4(0.f, 0.f, 0.f, 0.f);
    if (i < n4) reinterpret_cast<float4*>(g_sum)[i] = z;
    if (i < N_NODES) g_deg[i] = 0.f;
}

// ---------------------------------------------------------------------------
// Kernel 2: edge scatter. One warp per edge: each lane handles one float4 of
// the 128-float row. Vector f32 atomics (red.global.add.v4.f32, sm_90+).
// ---------------------------------------------------------------------------
__global__ void __launch_bounds__(256) scatter_kernel(
    const float4* __restrict__ x4,
    const int* __restrict__ src,
    const int* __restrict__ dst)
{
    int gw = (blockIdx.x * blockDim.x + threadIdx.x) >> 5;
    int lane = threadIdx.x & 31;
    if (gw >= N_EDGES) return;
    int s = __ldg(&src[gw]);
    int d = __ldg(&dst[gw]);
    float4 v = x4[(size_t)s * (D / 4) + lane];
    float4* p = reinterpret_cast<float4*>(g_sum) + (size_t)d * (D / 4) + lane;
    asm volatile("red.global.add.v4.f32 [%0], {%1,%2,%3,%4};"
                 :: "l"(p), "f"(v.x), "f"(v.y), "f"(v.z), "f"(v.w)
                 : "memory");
    if (lane == 0) atomicAdd(&g_deg[d], 1.0f);
}

// ---------------------------------------------------------------------------
// Kernel 3: fused GEMM + epilogue.
// out = x + relu( (g_sum/deg) @ W_l + x @ W_r + b )
// Viewed as A[50000 x 256] @ B[256 x 128] with A = [mean | x], B = [W_l ; W_r].
// Block: 128-row tile, full 128-col N, 256 threads, 8x8 micro-tile per thread.
// Packed fp32x2 FMA (fma.rn.f32x2) for 2x FFMA issue rate on sm_103a.
// ---------------------------------------------------------------------------
#define BM 128
#define KC 16
#define KTOT 256

union F2U { float2 f; unsigned long long u; };

__device__ __forceinline__ unsigned long long splat2(float v) {
    unsigned long long r;
    asm("mov.b64 %0, {%1, %1};" : "=l"(r) : "f"(v));
    return r;
}
__device__ __forceinline__ void fma2(unsigned long long& acc,
                                     unsigned long long a,
                                     unsigned long long b) {
    asm("fma.rn.f32x2 %0, %1, %2, %0;" : "+l"(acc) : "l"(a), "l"(b));
}

__global__ void __launch_bounds__(256, 1) gemm_kernel(
    const float* __restrict__ x,
    const float* __restrict__ Wl,
    const float* __restrict__ bias,
    const float* __restrict__ Wr,
    float* __restrict__ out)
{
    extern __shared__ float smem[];
    float* Bs = smem;                     // KTOT * 128 floats (128 KB)
    float* As = smem + KTOT * 128;        // KC * 128 floats (8 KB), layout [k][m]
    float* bs = As + KC * 128;            // 128 floats

    const int tid = threadIdx.x;
    const int row0 = blockIdx.x * BM;

    // --- Load stacked weights [W_l ; W_r] into Bs[k][n] (row-major, direct copy)
    {
        const float4* wl4 = reinterpret_cast<const float4*>(Wl);
        const float4* wr4 = reinterpret_cast<const float4*>(Wr);
        float4* Bs4 = reinterpret_cast<float4*>(Bs);
        #pragma unroll
        for (int i = 0; i < 16; i++)               // 128*128/4 = 4096 float4
            Bs4[tid + 256 * i] = wl4[tid + 256 * i];
        #pragma unroll
        for (int i = 0; i < 16; i++)
            Bs4[4096 + tid + 256 * i] = wr4[tid + 256 * i];
        if (tid < 128) bs[tid] = bias[tid];
    }

    const int tx = tid & 15;     // n-dim thread coord
    const int ty = tid >> 4;     // m-dim thread coord
    const int tx8 = tx * 8;
    const int ty8 = ty * 8;

    // acc[m][n2]: 8 m-rows x 4 packed n-pairs = 8x8 floats
    unsigned long long acc[8][4];
    #pragma unroll
    for (int i = 0; i < 8; i++)
        #pragma unroll
        for (int j = 0; j < 4; j++)
            acc[i][j] = 0ull;

    // A-load assignment: 256 threads cover 128 m x 4 float4-columns of a KC=16 chunk
    const int am  = tid & 127;
    const int akq = tid >> 7;            // 0 or 1
    int ar = row0 + am;
    if (ar >= N_NODES) ar = N_NODES - 1; // clamp (stores are guarded later)
    const float rdeg = 1.0f / fmaxf(g_deg[ar], 1.0f);
    const float4* sum4row = reinterpret_cast<const float4*>(g_sum + (size_t)ar * D);
    const float4* x4row   = reinterpret_cast<const float4*>(x + (size_t)ar * D);

    #pragma unroll 1
    for (int kt = 0; kt < KTOT / KC; kt++) {
        const int k0 = kt * KC;
        const bool is_mean = (k0 < 128);
        const float4* srow = is_mean ? sum4row : x4row;
        const float sc = is_mean ? rdeg : 1.0f;
        const int kb4 = (is_mean ? k0 : (k0 - 128)) >> 2;  // chunk base in float4

        // Load & transpose A chunk into As[k][m], scaling mean rows by 1/deg
        #pragma unroll
        for (int i = 0; i < 2; i++) {
            int kk4 = akq * 2 + i;       // 0..3
            float4 v = srow[kb4 + kk4];
            int kk = kk4 * 4;
            As[(kk + 0) * 128 + am] = v.x * sc;
            As[(kk + 1) * 128 + am] = v.y * sc;
            As[(kk + 2) * 128 + am] = v.z * sc;
            As[(kk + 3) * 128 + am] = v.w * sc;
        }
        __syncthreads();

        #pragma unroll
        for (int kk = 0; kk < KC; kk++) {
            const float4 a0 = *reinterpret_cast<const float4*>(&As[kk * 128 + ty8]);
            const float4 a1 = *reinterpret_cast<const float4*>(&As[kk * 128 + ty8 + 4]);
            const float4 b0 = *reinterpret_cast<const float4*>(&Bs[(k0 + kk) * 128 + tx8]);
            const float4 b1 = *reinterpret_cast<const float4*>(&Bs[(k0 + kk) * 128 + tx8 + 4]);

            unsigned long long bp[4];
            { F2U u; u.f = make_float2(b0.x, b0.y); bp[0] = u.u; }
            { F2U u; u.f = make_float2(b0.z, b0.w); bp[1] = u.u; }
            { F2U u; u.f = make_float2(b1.x, b1.y); bp[2] = u.u; }
            { F2U u; u.f = make_float2(b1.z, b1.w); bp[3] = u.u; }

            float av[8] = {a0.x, a0.y, a0.z, a0.w, a1.x, a1.y, a1.z, a1.w};
            #pragma unroll
            for (int m = 0; m < 8; m++) {
                unsigned long long as_ = splat2(av[m]);
                #pragma unroll
                for (int j = 0; j < 4; j++)
                    fma2(acc[m][j], as_, bp[j]);
            }
        }
        __syncthreads();
    }

    // --- Epilogue: out = x + relu(acc + bias)
    const float4 ba = *reinterpret_cast<const float4*>(&bs[tx8]);
    const float4 bb = *reinterpret_cast<const float4*>(&bs[tx8 + 4]);
    #pragma unroll
    for (int m = 0; m < 8; m++) {
        int r = row0 + ty8 + m;
        if (r < N_NODES) {
            const float4* xr = reinterpret_cast<const float4*>(x + (size_t)r * D + tx8);
            float4* outr = reinterpret_cast<float4*>(out + (size_t)r * D + tx8);
            float4 xa = xr[0], xb = xr[1];
            F2U u; float4 o;
            u.u = acc[m][0];
            o.x = xa.x + fmaxf(u.f.x + ba.x, 0.f);
            o.y = xa.y + fmaxf(u.f.y + ba.y, 0.f);
            u.u = acc[m][1];
            o.z = xa.z + fmaxf(u.f.x + ba.z, 0.f);
            o.w = xa.w + fmaxf(u.f.y + ba.w, 0.f);
            outr[0] = o;
            u.u = acc[m][2];
            o.x = xb.x + fmaxf(u.f.x + bb.x, 0.f);
            o.y = xb.y + fmaxf(u.f.y + bb.y, 0.f);
            u.u = acc[m][3];
            o.z = xb.z + fmaxf(u.f.x + bb.z, 0.f);
            o.w = xb.w + fmaxf(u.f.y + bb.w, 0.f);
            outr[1] = o;
        }
    }
}

// ---------------------------------------------------------------------------
extern "C" void kernel_launch(void* const* d_in, const int* in_sizes, int n_in,
                              void* d_out, int out_size)
{
    const float* x  = (const float*)d_in[0];
    const int*   ei = (const int*)d_in[1];      // [2, E]: src = ei[0:E], dst = ei[E:2E]
    const float* Wl = (const float*)d_in[2];
    const float* bl = (const float*)d_in[3];
    const float* Wr = (const float*)d_in[4];
    float* out = (float*)d_out;

    // 1) zero accumulators
    {
        const int n4 = N_NODES * D / 4;  // 1.6M, also covers N_NODES deg entries
        zero_kernel<<<(n4 + 255) / 256, 256>>>();
    }

    // 2) edge scatter: one warp per edge
    {
        long long threads = (long long)N_EDGES * 32;
        int blocks = (int)((threads + 255) / 256);
        scatter_kernel<<<blocks, 256>>>(
            reinterpret_cast<const float4*>(x), ei, ei + N_EDGES);
    }

    // 3) fused GEMM + epilogue
    {
        const int smem_bytes = (KTOT * 128 + KC * 128 + 128) * sizeof(float); // ~140 KB
        cudaFuncSetAttribute(gemm_kernel,
                             cudaFuncAttributeMaxDynamicSharedMemorySize,
                             smem_bytes);
        int grid = (N_NODES + BM - 1) / BM;   // 391
        gemm_kernel<<<grid, 256, smem_bytes>>>(x, Wl, bl, Wr, out);
    }
}

// round 2
// speedup vs baseline: 1.2003x; 1.2003x over previous
#include <cuda_runtime.h>
#include <cstdint>

#define N_NODES 50000
#define D 128
#define N_EDGES 625000
#define SCAN_BLK 256
#define N_SCAN_BLOCKS ((N_NODES + SCAN_BLK - 1) / SCAN_BLK)   // 196

// Scratch (no cudaMalloc allowed)
__device__ float g_mean[(size_t)N_NODES * D];   // 25.6 MB: mean-aggregated neighbors
__device__ int   g_cnt[N_NODES];                // degree (histogram)
__device__ int   g_start[N_NODES];              // CSR row start (exclusive scan)
__device__ int   g_pos[N_NODES];                // fill cursor
__device__ int   g_bsum[N_SCAN_BLOCKS];         // per-block scan sums
__device__ int   g_boff[N_SCAN_BLOCKS];         // scanned block offsets
__device__ int   g_esrc[N_EDGES];               // dst-sorted src indices

// ---------------------------------------------------------------------------
// 1) zero the degree histogram
// ---------------------------------------------------------------------------
__global__ void zero_cnt_kernel() {
    int i = blockIdx.x * blockDim.x + threadIdx.x;
    if (i < N_NODES) g_cnt[i] = 0;
}

// ---------------------------------------------------------------------------
// 2) histogram of dst (degree)
// ---------------------------------------------------------------------------
__global__ void hist_kernel(const int* __restrict__ dst) {
    int i = blockIdx.x * blockDim.x + threadIdx.x;
    if (i < N_EDGES) atomicAdd(&g_cnt[dst[i]], 1);
}

// ---------------------------------------------------------------------------
// 3a) per-block exclusive scan of g_cnt, block sums to g_bsum
// ---------------------------------------------------------------------------
__global__ void scan1_kernel() {
    __shared__ int sh[SCAN_BLK];
    int t = threadIdx.x;
    int i = blockIdx.x * SCAN_BLK + t;
    int v = (i < N_NODES) ? g_cnt[i] : 0;
    sh[t] = v;
    __syncthreads();
    #pragma unroll
    for (int off = 1; off < SCAN_BLK; off <<= 1) {
        int t2 = (t >= off) ? sh[t - off] : 0;
        __syncthreads();
        sh[t] += t2;
        __syncthreads();
    }
    if (i < N_NODES) g_start[i] = sh[t] - v;          // exclusive within block
    if (t == SCAN_BLK - 1) g_bsum[blockIdx.x] = sh[t];
}

// ---------------------------------------------------------------------------
// 3b) exclusive scan of the 196 block sums (single block)
// ---------------------------------------------------------------------------
__global__ void scan2_kernel() {
    __shared__ int sh[SCAN_BLK];
    int t = threadIdx.x;
    int v = (t < N_SCAN_BLOCKS) ? g_bsum[t] : 0;
    sh[t] = v;
    __syncthreads();
    #pragma unroll
    for (int off = 1; off < SCAN_BLK; off <<= 1) {
        int t2 = (t >= off) ? sh[t - off] : 0;
        __syncthreads();
        sh[t] += t2;
        __syncthreads();
    }
    if (t < N_SCAN_BLOCKS) g_boff[t] = sh[t] - v;
}

// ---------------------------------------------------------------------------
// 3c) add block offsets; init fill cursors
// ---------------------------------------------------------------------------
__global__ void scan3_kernel() {
    int i = blockIdx.x * blockDim.x + threadIdx.x;
    if (i < N_NODES) {
        int s = g_start[i] + g_boff[i >> 8];
        g_start[i] = s;
        g_pos[i] = s;
    }
}

// ---------------------------------------------------------------------------
// 4) fill dst-sorted edge list
// ---------------------------------------------------------------------------
__global__ void fill_kernel(const int* __restrict__ src,
                            const int* __restrict__ dst) {
    int i = blockIdx.x * blockDim.x + threadIdx.x;
    if (i < N_EDGES) {
        int slot = atomicAdd(&g_pos[dst[i]], 1);
        g_esrc[slot] = src[i];
    }
}

// ---------------------------------------------------------------------------
// 5) pull-aggregate: one warp per node, lane = one float4 column.
//    MLP=4 manual pipelining on the neighbor-row loads. Writes mean once.
// ---------------------------------------------------------------------------
__global__ void __launch_bounds__(256) gather_kernel(const float4* __restrict__ x4)
{
    int node = (blockIdx.x * blockDim.x + threadIdx.x) >> 5;
    int lane = threadIdx.x & 31;
    if (node >= N_NODES) return;

    int start = g_start[node];
    int deg   = g_cnt[node];
    int end   = start + deg;

    float4 acc = make_float4(0.f, 0.f, 0.f, 0.f);
    int e = start;
    // 4-deep pipeline
    for (; e + 4 <= end; e += 4) {
        int i0 = __ldg(&g_esrc[e]);
        int i1 = __ldg(&g_esrc[e + 1]);
        int i2 = __ldg(&g_esrc[e + 2]);
        int i3 = __ldg(&g_esrc[e + 3]);
        float4 v0 = x4[(size_t)i0 * (D / 4) + lane];
        float4 v1 = x4[(size_t)i1 * (D / 4) + lane];
        float4 v2 = x4[(size_t)i2 * (D / 4) + lane];
        float4 v3 = x4[(size_t)i3 * (D / 4) + lane];
        float4 s01 = make_float4(v0.x + v1.x, v0.y + v1.y, v0.z + v1.z, v0.w + v1.w);
        float4 s23 = make_float4(v2.x + v3.x, v2.y + v3.y, v2.z + v3.z, v2.w + v3.w);
        acc.x += s01.x + s23.x;
        acc.y += s01.y + s23.y;
        acc.z += s01.z + s23.z;
        acc.w += s01.w + s23.w;
    }
    for (; e < end; e++) {
        int i0 = __ldg(&g_esrc[e]);
        float4 v0 = x4[(size_t)i0 * (D / 4) + lane];
        acc.x += v0.x; acc.y += v0.y; acc.z += v0.z; acc.w += v0.w;
    }

    float rdeg = 1.0f / fmaxf((float)deg, 1.0f);
    acc.x *= rdeg; acc.y *= rdeg; acc.z *= rdeg; acc.w *= rdeg;
    reinterpret_cast<float4*>(g_mean)[(size_t)node * (D / 4) + lane] = acc;
}

// ---------------------------------------------------------------------------
// 6) fused GEMM + epilogue:
//    out = x + relu( g_mean @ W_l + x @ W_r + b )
//    A[50000 x 256] = [mean | x], B[256 x 128] = [W_l ; W_r]
//    128-row tile, 256 threads, 8x8 micro-tile, packed fp32x2 FMA.
// ---------------------------------------------------------------------------
#define BM 128
#define KC 16
#define KTOT 256

union F2U { float2 f; unsigned long long u; };

__device__ __forceinline__ unsigned long long splat2(float v) {
    unsigned long long r;
    asm("mov.b64 %0, {%1, %1};" : "=l"(r) : "f"(v));
    return r;
}
__device__ __forceinline__ void fma2(unsigned long long& acc,
                                     unsigned long long a,
                                     unsigned long long b) {
    asm("fma.rn.f32x2 %0, %1, %2, %0;" : "+l"(acc) : "l"(a), "l"(b));
}

__global__ void __launch_bounds__(256, 1) gemm_kernel(
    const float* __restrict__ x,
    const float* __restrict__ Wl,
    const float* __restrict__ bias,
    const float* __restrict__ Wr,
    float* __restrict__ out)
{
    extern __shared__ float smem[];
    float* Bs = smem;                     // KTOT * 128 floats (128 KB)
    float* As = smem + KTOT * 128;        // KC * 128 floats (8 KB), layout [k][m]
    float* bs = As + KC * 128;            // 128 floats

    const int tid = threadIdx.x;
    const int row0 = blockIdx.x * BM;

    // Stacked weights [W_l ; W_r] into Bs[k][n]
    {
        const float4* wl4 = reinterpret_cast<const float4*>(Wl);
        const float4* wr4 = reinterpret_cast<const float4*>(Wr);
        float4* Bs4 = reinterpret_cast<float4*>(Bs);
        #pragma unroll
        for (int i = 0; i < 16; i++)
            Bs4[tid + 256 * i] = wl4[tid + 256 * i];
        #pragma unroll
        for (int i = 0; i < 16; i++)
            Bs4[4096 + tid + 256 * i] = wr4[tid + 256 * i];
        if (tid < 128) bs[tid] = bias[tid];
    }

    const int tx = tid & 15;
    const int ty = tid >> 4;
    const int tx8 = tx * 8;
    const int ty8 = ty * 8;

    unsigned long long acc[8][4];
    #pragma unroll
    for (int i = 0; i < 8; i++)
        #pragma unroll
        for (int j = 0; j < 4; j++)
            acc[i][j] = 0ull;

    const int am  = tid & 127;
    const int akq = tid >> 7;
    int ar = row0 + am;
    if (ar >= N_NODES) ar = N_NODES - 1;
    const float4* mean4row = reinterpret_cast<const float4*>(g_mean + (size_t)ar * D);
    const float4* x4row    = reinterpret_cast<const float4*>(x + (size_t)ar * D);

    #pragma unroll 1
    for (int kt = 0; kt < KTOT / KC; kt++) {
        const int k0 = kt * KC;
        const bool is_mean = (k0 < 128);
        const float4* srow = is_mean ? mean4row : x4row;
        const int kb4 = (is_mean ? k0 : (k0 - 128)) >> 2;

        #pragma unroll
        for (int i = 0; i < 2; i++) {
            int kk4 = akq * 2 + i;
            float4 v = srow[kb4 + kk4];
            int kk = kk4 * 4;
            As[(kk + 0) * 128 + am] = v.x;
            As[(kk + 1) * 128 + am] = v.y;
            As[(kk + 2) * 128 + am] = v.z;
            As[(kk + 3) * 128 + am] = v.w;
        }
        __syncthreads();

        #pragma unroll
        for (int kk = 0; kk < KC; kk++) {
            const float4 a0 = *reinterpret_cast<const float4*>(&As[kk * 128 + ty8]);
            const float4 a1 = *reinterpret_cast<const float4*>(&As[kk * 128 + ty8 + 4]);
            const float4 b0 = *reinterpret_cast<const float4*>(&Bs[(k0 + kk) * 128 + tx8]);
            const float4 b1 = *reinterpret_cast<const float4*>(&Bs[(k0 + kk) * 128 + tx8 + 4]);

            unsigned long long bp[4];
            { F2U u; u.f = make_float2(b0.x, b0.y); bp[0] = u.u; }
            { F2U u; u.f = make_float2(b0.z, b0.w); bp[1] = u.u; }
            { F2U u; u.f = make_float2(b1.x, b1.y); bp[2] = u.u; }
            { F2U u; u.f = make_float2(b1.z, b1.w); bp[3] = u.u; }

            float av[8] = {a0.x, a0.y, a0.z, a0.w, a1.x, a1.y, a1.z, a1.w};
            #pragma unroll
            for (int m = 0; m < 8; m++) {
                unsigned long long as_ = splat2(av[m]);
                #pragma unroll
                for (int j = 0; j < 4; j++)
                    fma2(acc[m][j], as_, bp[j]);
            }
        }
        __syncthreads();
    }

    const float4 ba = *reinterpret_cast<const float4*>(&bs[tx8]);
    const float4 bb = *reinterpret_cast<const float4*>(&bs[tx8 + 4]);
    #pragma unroll
    for (int m = 0; m < 8; m++) {
        int r = row0 + ty8 + m;
        if (r < N_NODES) {
            const float4* xr = reinterpret_cast<const float4*>(x + (size_t)r * D + tx8);
            float4* outr = reinterpret_cast<float4*>(out + (size_t)r * D + tx8);
            float4 xa = xr[0], xb = xr[1];
            F2U u; float4 o;
            u.u = acc[m][0];
            o.x = xa.x + fmaxf(u.f.x + ba.x, 0.f);
            o.y = xa.y + fmaxf(u.f.y + ba.y, 0.f);
            u.u = acc[m][1];
            o.z = xa.z + fmaxf(u.f.x + ba.z, 0.f);
            o.w = xa.w + fmaxf(u.f.y + ba.w, 0.f);
            outr[0] = o;
            u.u = acc[m][2];
            o.x = xb.x + fmaxf(u.f.x + bb.x, 0.f);
            o.y = xb.y + fmaxf(u.f.y + bb.y, 0.f);
            u.u = acc[m][3];
            o.z = xb.z + fmaxf(u.f.x + bb.z, 0.f);
            o.w = xb.w + fmaxf(u.f.y + bb.w, 0.f);
            outr[1] = o;
        }
    }
}

// ---------------------------------------------------------------------------
extern "C" void kernel_launch(void* const* d_in, const int* in_sizes, int n_in,
                              void* d_out, int out_size)
{
    const float* x  = (const float*)d_in[0];
    const int*   ei = (const int*)d_in[1];      // [2, E]: src = ei[0:E], dst = ei[E:2E]
    const float* Wl = (const float*)d_in[2];
    const float* bl = (const float*)d_in[3];
    const float* Wr = (const float*)d_in[4];
    float* out = (float*)d_out;

    const int* src = ei;
    const int* dst = ei + N_EDGES;

    zero_cnt_kernel<<<(N_NODES + 255) / 256, 256>>>();
    hist_kernel<<<(N_EDGES + 255) / 256, 256>>>(dst);
    scan1_kernel<<<N_SCAN_BLOCKS, SCAN_BLK>>>();
    scan2_kernel<<<1, SCAN_BLK>>>();
    scan3_kernel<<<(N_NODES + 255) / 256, 256>>>();
    fill_kernel<<<(N_EDGES + 255) / 256, 256>>>(src, dst);

    {
        long long threads = (long long)N_NODES * 32;
        int blocks = (int)((threads + 255) / 256);
        gather_kernel<<<blocks, 256>>>(reinterpret_cast<const float4*>(x));
    }

    {
        const int smem_bytes = (KTOT * 128 + KC * 128 + 128) * sizeof(float);
        cudaFuncSetAttribute(gemm_kernel,
                             cudaFuncAttributeMaxDynamicSharedMemorySize,
                             smem_bytes);
        int grid = (N_NODES + BM - 1) / BM;
        gemm_kernel<<<grid, 256, smem_bytes>>>(x, Wl, bl, Wr, out);
    }
}